// round 13
// baseline (speedup 1.0000x reference)
#include <cuda_runtime.h>
#include <cuda_bf16.h>
#include <cstdint>

// ============================================================================
// SourceAwareContrastiveLoss, GB300 — base sm_103 ISA.
// R13: GEMM restored to pure R10 form (2 CTA/SM, no appended tail);
// reduceS rewritten as a fully-coalesced column-sum (thread-owns-output);
// inlined label-dtype detect + last-block final reduce kept from R12.
//
// loss = -(1/N) sum_i (scale*img_i·(S_{c(i)} - text_i) - cnt_i*lse_i)/cnt_i
// lse_i = logsumexp_j scale*(img_i·text_j)
// ============================================================================

#define NROWS 8192
#define DDIM  512
#define NSRC  8
#define BM    128
#define BN    128
#define BK    64
#define KSTEPS (DDIM / BK)     // 8 K-steps per pass
#define NCHUNKS 16             // columns split into 16 chunks of 512
#define TILES_PER_CHUNK 4      // 512 / 128
#define MAIN_THREADS 256
#define NSTAGES 3

#define TSTRIDE 144                    // 128 B data + 16 B pad (conflict-free ldmatrix)
#define TILEB   (128 * TSTRIDE)        // 18432 B per operand tile
#define STAGEB  (2 * TILEB)            // A + B
#define SM_MAIN_BYTES (NSTAGES * STAGEB)   // 110592 B  (x2 CTAs = 221184 <= 228KB)

#define SRC_BLKS 128                   // srcsum partial blocks (64 rows each)

// ---------------- device scratch (static: no runtime allocation) -----------
__device__ __nv_bfloat16 g_img_bf [NROWS * DDIM];   // scale * img, bf16
__device__ __nv_bfloat16 g_text_bf[NROWS * DDIM];
__device__ float g_Spart[SRC_BLKS * NSRC * DDIM];
__device__ float g_S[NSRC * DDIM];
__device__ int   g_cntPart[SRC_BLKS * NSRC];
__device__ int   g_cnt[NSRC];
__device__ float g_pmax[NROWS * NCHUNKS];
__device__ float g_psum[NROWS * NCHUNKS];
__device__ float g_ploss[1024];
__device__ int   g_done;               // static-init 0; reset by last block

// ---------------- label handling --------------------------------------------
// Warp-collective dtype detect: int64 labels in [0,8) have all odd 32-bit
// words zero; 32 random int32 labels all-zero has prob 8^-32. Deterministic.
__device__ __forceinline__ int detect_lab64_warp(const void* labels, int lane) {
    int w = ((const int*)labels)[2 * lane + 1];
    unsigned nb = __ballot_sync(0xffffffffu, w != 0);
    return nb == 0u;
}

__device__ __forceinline__ int get_label(const void* p, int i, int lab64) {
    int v = lab64 ? (int)((const long long*)p)[i] : ((const int*)p)[i];
    return (v < 0) ? 0 : (v >= NSRC ? NSRC - 1 : v);
}

// ---------------- PTX helpers ----------------------------------------------
__device__ __forceinline__ uint32_t smem_to_u32(const void* p) {
    uint32_t a;
    asm("{ .reg .u64 t; cvta.to.shared.u64 t, %1; cvt.u32.u64 %0, t; }"
        : "=r"(a) : "l"(p));
    return a;
}

#define CP_ASYNC16(saddr, gptr) \
    asm volatile("cp.async.cg.shared.global [%0], [%1], 16;" \
        :: "r"(saddr), "l"(gptr))
#define CP_COMMIT() asm volatile("cp.async.commit_group;")
#define CP_WAIT(n)  asm volatile("cp.async.wait_group %0;" :: "n"(n))

#define LDMATRIX_X4(r, addr) \
    asm volatile("ldmatrix.sync.aligned.m8n8.x4.shared.b16 {%0,%1,%2,%3}, [%4];" \
        : "=r"((r)[0]), "=r"((r)[1]), "=r"((r)[2]), "=r"((r)[3]) : "r"(addr))

#define MMA16816(d, a, b) \
    asm volatile("mma.sync.aligned.m16n8k16.row.col.f32.bf16.bf16.f32 " \
        "{%0,%1,%2,%3}, {%4,%5,%6,%7}, {%8,%9}, {%0,%1,%2,%3};" \
        : "+f"((d)[0]), "+f"((d)[1]), "+f"((d)[2]), "+f"((d)[3]) \
        : "r"((a)[0]), "r"((a)[1]), "r"((a)[2]), "r"((a)[3]), \
          "r"((b)[0]), "r"((b)[1]))

// ---------------- prologue kernels ------------------------------------------

// convert one tensor to bf16; destination selected IN DEVICE CODE (which:
// 0 = img (scaled), 1 = text). Never pass __device__ symbols from host.
__global__ void convert_kernel(const float* __restrict__ src,
                               const float* __restrict__ scale_ptr,
                               int which) {
    const int total4 = NROWS * DDIM / 4;
    int i = blockIdx.x * blockDim.x + threadIdx.x;
    if (i >= total4) return;
    __nv_bfloat16* dst = which ? g_text_bf : g_img_bf;
    float s = which ? 1.f : *scale_ptr;
    float4 v = ((const float4*)src)[i];
    __nv_bfloat162 lo = __floats2bfloat162_rn(s * v.x, s * v.y);
    __nv_bfloat162 hi = __floats2bfloat162_rn(s * v.z, s * v.w);
    ((uint2*)dst)[i] = make_uint2(*(uint32_t*)&lo, *(uint32_t*)&hi);
}

// per-64-row partial class sums of text features (128 blocks, coalesced)
__global__ void srcsum_kernel(const float* __restrict__ text,
                              const void* __restrict__ labels) {
    __shared__ int slab[64];
    __shared__ int s_is64;
    const int k = threadIdx.x;          // 512 threads, one feature column each
    const int r0 = blockIdx.x * 64;
    if (k < 32) {
        int is64 = detect_lab64_warp(labels, k);
        if (k == 0) s_is64 = is64;
    }
    __syncthreads();
    if (k < 64) slab[k] = get_label(labels, r0 + k, s_is64);
    __syncthreads();
    float s[NSRC];
#pragma unroll
    for (int c = 0; c < NSRC; c++) s[c] = 0.f;
    for (int r = 0; r < 64; r++) {
        int lab = slab[r];
        float v = text[(r0 + r) * DDIM + k];
#pragma unroll
        for (int c = 0; c < NSRC; c++) s[c] += (lab == c) ? v : 0.f;
    }
#pragma unroll
    for (int c = 0; c < NSRC; c++)
        g_Spart[(blockIdx.x * NSRC + c) * DDIM + k] = s[c];
    if (k < NSRC) {
        int cnt = 0;
        for (int r = 0; r < 64; r++) cnt += (slab[r] == k);
        g_cntPart[blockIdx.x * NSRC + k] = cnt;
    }
}

// fully-coalesced column sum: thread t owns output (blockIdx*256 + t),
// loops over the 128 partial blocks. Every warp load is one 128B line.
__global__ void reduceS_kernel() {
    const int out = blockIdx.x * 256 + threadIdx.x;   // 16 blocks x 256 = 4096
    float a = 0.f;
#pragma unroll 8
    for (int p = 0; p < SRC_BLKS; p++)
        a += g_Spart[p * (NSRC * DDIM) + out];
    g_S[out] = a;

    if (blockIdx.x == 0 && threadIdx.x < NSRC) {
        int c = 0;
        for (int p = 0; p < SRC_BLKS; p++)
            c += g_cntPart[p * NSRC + threadIdx.x];
        g_cnt[threadIdx.x] = c;
    }
}

// ---------------- main fused GEMM + online logsumexp ------------------------

// issue cp.async for one BK=64 k-slice (A + B tiles) into `stage`
__device__ __forceinline__ void load_tiles(uint32_t sb, int stage,
                                           int m0, int n0, int tid, int k0) {
#pragma unroll
    for (int i = 0; i < 8; i++) {
        int idx    = i * MAIN_THREADS + tid;  // 0..2047
        int tile   = idx >> 10;               // 0=A, 1=B
        int within = idx & 1023;
        int row    = within >> 3;             // 0..127
        int c8     = within & 7;              // 16B chunks
        const __nv_bfloat16* base = tile ? g_text_bf : g_img_bf;
        int grow = (tile ? n0 : m0) + row;
        const __nv_bfloat16* g = base + grow * DDIM + k0 + c8 * 8;
        uint32_t s = sb + stage * STAGEB + tile * TILEB + row * TSTRIDE + c8 * 16;
        CP_ASYNC16(s, g);
    }
}

// grid = 1024 CTAs: (mt 0..63) x (chunk 0..15); each CTA: 128 rows x 512 cols
// 8 warps: wm 0..3 (32-row strip), wn 0..1 (64-col strip)
__global__ void __launch_bounds__(MAIN_THREADS, 2)
gemm_lse_kernel() {
    extern __shared__ char smem[];
    uint32_t sb = smem_to_u32(smem);
    const int tid  = threadIdx.x;
    const int warp = tid >> 5;
    const int lane = tid & 31;
    const int wm = warp >> 1;           // 0..3  (M subtile)
    const int wn = warp & 1;            // 0..1  (N subtile)
    const int mt    = blockIdx.x & 63;
    const int chunk = blockIdx.x >> 6;
    const int m0    = mt * BM;
    const int nbase = chunk * 512;
    const float NEG_INF = __int_as_float(0xff800000);

    // ldmatrix per-lane address offsets (within an operand tile)
    const int a_row = wm * 32 + (lane & 15);                           // + tm*16
    const uint32_t a_off = (uint32_t)(a_row * TSTRIDE + ((lane >> 4) << 4));
    const int b_row = wn * 64 + (lane & 7) + (((lane >> 4) & 1) << 3); // + tn2*16
    const uint32_t b_off = (uint32_t)(b_row * TSTRIDE + (((lane >> 3) & 1) << 4));

    // running per-row logsumexp state: [tm][half]
    float rm[2][2], rs[2][2];
#pragma unroll
    for (int a = 0; a < 2; a++)
#pragma unroll
        for (int b = 0; b < 2; b++) { rm[a][b] = NEG_INF; rs[a][b] = 0.f; }

    for (int t = 0; t < TILES_PER_CHUNK; t++) {
        const int n0 = nbase + t * BN;

        float acc[2][8][4];        // [tm][tn][q] — 64 regs
#pragma unroll
        for (int i = 0; i < 2; i++)
#pragma unroll
            for (int j = 0; j < 8; j++)
#pragma unroll
                for (int q = 0; q < 4; q++) acc[i][j][q] = 0.f;

        // all warps must be done with previous pass's stages before reloading
        __syncthreads();
        load_tiles(sb, 0, m0, n0, tid, 0);  CP_COMMIT();
        load_tiles(sb, 1, m0, n0, tid, BK); CP_COMMIT();

        for (int ks = 0; ks < KSTEPS; ks++) {
            CP_WAIT(1);            // stage ks resident
            __syncthreads();       // all warps finished compute(ks-1)
            if (ks + 2 < KSTEPS)
                load_tiles(sb, (ks + 2) % NSTAGES, m0, n0, tid, (ks + 2) * BK);
            CP_COMMIT();           // may be empty (keeps wait count uniform)

            const uint32_t tb = sb + (uint32_t)((ks % NSTAGES) * STAGEB);
#pragma unroll
            for (int ksub = 0; ksub < 4; ksub++) {
                const uint32_t koff = (uint32_t)(ksub * 32);  // 16 elems = 32 B
                uint32_t afrag[2][4];
#pragma unroll
                for (int tm = 0; tm < 2; tm++) {
                    uint32_t addr = tb + a_off + (uint32_t)(tm * 16 * TSTRIDE) + koff;
                    LDMATRIX_X4(afrag[tm], addr);
                }
                uint32_t bfrag[8][2];
#pragma unroll
                for (int tn2 = 0; tn2 < 4; tn2++) {
                    uint32_t addr = tb + TILEB + b_off
                                  + (uint32_t)(tn2 * 16 * TSTRIDE) + koff;
                    uint32_t r[4];
                    LDMATRIX_X4(r, addr);
                    bfrag[2 * tn2][0] = r[0];     bfrag[2 * tn2][1] = r[1];
                    bfrag[2 * tn2 + 1][0] = r[2]; bfrag[2 * tn2 + 1][1] = r[3];
                }
#pragma unroll
                for (int tm = 0; tm < 2; tm++)
#pragma unroll
                    for (int tn = 0; tn < 8; tn++)
                        MMA16816(acc[tm][tn], afrag[tm], bfrag[tn]);
            }
        }

        // epilogue: online per-row max/sumexp over this 128-col tile
#pragma unroll
        for (int tm = 0; tm < 2; tm++) {
#pragma unroll
            for (int half = 0; half < 2; half++) {
                float mx = NEG_INF;
#pragma unroll
                for (int tn = 0; tn < 8; tn++)
                    mx = fmaxf(mx, fmaxf(acc[tm][tn][half * 2],
                                         acc[tm][tn][half * 2 + 1]));
                mx = fmaxf(mx, __shfl_xor_sync(0xffffffffu, mx, 1));
                mx = fmaxf(mx, __shfl_xor_sync(0xffffffffu, mx, 2));
                float nm = fmaxf(rm[tm][half], mx);
                float s = 0.f;
#pragma unroll
                for (int tn = 0; tn < 8; tn++) {
                    s += __expf(acc[tm][tn][half * 2]     - nm);
                    s += __expf(acc[tm][tn][half * 2 + 1] - nm);
                }
                s += __shfl_xor_sync(0xffffffffu, s, 1);
                s += __shfl_xor_sync(0xffffffffu, s, 2);
                rs[tm][half] = rs[tm][half] * __expf(rm[tm][half] - nm) + s;
                rm[tm][half] = nm;
            }
        }
    }

    // merge the two N-warps (wn=0/1) per row and store chunk partials
    float* s_m = (float*)smem;            // [2][128] (reuse tile smem)
    float* s_s = s_m + 256;
    __syncthreads();
    if ((lane & 3) == 0) {
#pragma unroll
        for (int tm = 0; tm < 2; tm++)
#pragma unroll
            for (int half = 0; half < 2; half++) {
                int row = wm * 32 + tm * 16 + half * 8 + (lane >> 2);
                s_m[wn * 128 + row] = rm[tm][half];
                s_s[wn * 128 + row] = rs[tm][half];
            }
    }
    __syncthreads();
    if (tid < BM) {
        float ma = s_m[tid], mb = s_m[128 + tid];
        float M = fmaxf(ma, mb);
        float S = s_s[tid] * __expf(ma - M) + s_s[128 + tid] * __expf(mb - M);
        g_pmax[(m0 + tid) * NCHUNKS + chunk] = M;
        g_psum[(m0 + tid) * NCHUNKS + chunk] = S;
    }
}

// ---------------- per-row finalize + last-block final reduce ----------------
__global__ void finalize_rows(const float* __restrict__ img,
                              const float* __restrict__ text,
                              const void* __restrict__ labels,
                              const float* __restrict__ scale_ptr,
                              float* __restrict__ out) {
    __shared__ int s_is64;
    __shared__ float sh[8];
    __shared__ int s_last;
    __shared__ float red[256];

    const int warp = threadIdx.x >> 5;
    const int lane = threadIdx.x & 31;
    const int row  = blockIdx.x * 8 + warp;
    const float scale = *scale_ptr;

    if (threadIdx.x < 32) {
        int is64 = detect_lab64_warp(labels, lane);
        if (lane == 0) s_is64 = is64;
    }
    __syncthreads();

    const int c = get_label(labels, row, s_is64);
    const int cnt = g_cnt[c] - 1;

    float pm = (lane < NCHUNKS) ? g_pmax[row * NCHUNKS + lane] : __int_as_float(0xff800000);
    float M = pm;
#pragma unroll
    for (int o = 16; o; o >>= 1) M = fmaxf(M, __shfl_xor_sync(0xffffffffu, M, o));
    float ps = (lane < NCHUNKS) ? g_psum[row * NCHUNKS + lane] * __expf(pm - M) : 0.f;
#pragma unroll
    for (int o = 16; o; o >>= 1) ps += __shfl_xor_sync(0xffffffffu, ps, o);
    float lse = M + __logf(ps);

    // exact fp32 masked-sum dot: img_row · (S_c - text_row), float4 loads
    const float4* img4  = (const float4*)(img  + row * DDIM);
    const float4* txt4  = (const float4*)(text + row * DDIM);
    const float4* Sc4   = (const float4*)(g_S + c * DDIM);
    float d = 0.f;
#pragma unroll
    for (int g = 0; g < DDIM / 128; g++) {
        int k = g * 32 + lane;
        float4 a = img4[k], b = txt4[k], s4 = Sc4[k];
        d += a.x * (s4.x - b.x) + a.y * (s4.y - b.y)
           + a.z * (s4.z - b.z) + a.w * (s4.w - b.w);
    }
#pragma unroll
    for (int o = 16; o; o >>= 1) d += __shfl_xor_sync(0xffffffffu, d, o);

    if (lane == 0)
        sh[warp] = (cnt > 0) ? (scale * d - (float)cnt * lse) / (float)cnt : 0.f;
    __syncthreads();
    if (threadIdx.x == 0) {
        float a = 0.f;
#pragma unroll
        for (int w = 0; w < 8; w++) a += sh[w];
        g_ploss[blockIdx.x] = a;
        __threadfence();
        int old = atomicAdd(&g_done, 1);
        s_last = (old == 1023);
    }
    __syncthreads();

    // last block: deterministic final reduction of the 1024 partials
    if (s_last) {
        __threadfence();
        float a = 0.f;
        for (int i = threadIdx.x; i < 1024; i += 256) a += g_ploss[i];
        red[threadIdx.x] = a;
        __syncthreads();
        for (int s = 128; s; s >>= 1) {
            if (threadIdx.x < s) red[threadIdx.x] += red[threadIdx.x + s];
            __syncthreads();
        }
        if (threadIdx.x == 0) {
            out[0] = -red[0] / (float)NROWS;
            g_done = 0;                    // reset for next graph replay
        }
    }
}

// ---------------- launch ----------------------------------------------------
extern "C" void kernel_launch(void* const* d_in, const int* in_sizes, int n_in,
                              void* d_out, int out_size) {
    // Identify inputs by element count (robust to metadata ordering).
    const float* img   = nullptr;
    const float* text  = nullptr;
    const float* scale = nullptr;
    const void*  labels = nullptr;
    for (int i = 0; i < n_in; i++) {
        int s = in_sizes[i];
        if (s == NROWS * DDIM) {
            if (!img) img = (const float*)d_in[i];
            else      text = (const float*)d_in[i];
        } else if (s == 1) {
            scale = (const float*)d_in[i];
        } else if (s == NROWS) {
            labels = d_in[i];
        }
    }
    float* out = (float*)d_out;

    cudaFuncSetAttribute(gemm_lse_kernel,
                         cudaFuncAttributeMaxDynamicSharedMemorySize, SM_MAIN_BYTES);

    // 6 launches; gemm stays at capture slot 3.
    const int conv_blocks = (NROWS * DDIM / 4 + 255) / 256;
    convert_kernel<<<conv_blocks, 256>>>(img,  scale, 0);            // 0
    convert_kernel<<<conv_blocks, 256>>>(text, scale, 1);            // 1
    srcsum_kernel<<<SRC_BLKS, 512>>>(text, labels);                  // 2
    gemm_lse_kernel<<<1024, MAIN_THREADS, SM_MAIN_BYTES>>>();        // 3
    reduceS_kernel<<<16, 256>>>();                                   // 4
    finalize_rows<<<1024, 256>>>(img, text, labels, scale, out);     // 5
}

// round 14
// speedup vs baseline: 1.0198x; 1.0198x over previous
#include <cuda_runtime.h>
#include <cuda_bf16.h>
#include <cstdint>

// ============================================================================
// SourceAwareContrastiveLoss, GB300 — base sm_103 ISA.
// R14: wave-quantization fix — grid refined 1024 -> 4096 CTAs (one 128x128
// tile each; 13.8 waves instead of 3.46 on 296 resident slots). Same 2-CTA/SM
// 8-warp bf16 mma.sync engine; epilogue is now a one-shot tile max/sumexp.
//
// loss = -(1/N) sum_i (scale*img_i·(S_{c(i)} - text_i) - cnt_i*lse_i)/cnt_i
// lse_i = logsumexp_j scale*(img_i·text_j)
// ============================================================================

#define NROWS 8192
#define DDIM  512
#define NSRC  8
#define BM    128
#define BN    128
#define BK    64
#define KSTEPS (DDIM / BK)     // 8 K-steps per tile
#define NCHUNKS 64             // one partial per 128-column tile
#define MAIN_THREADS 256
#define NSTAGES 3

#define TSTRIDE 144                    // 128 B data + 16 B pad (conflict-free ldmatrix)
#define TILEB   (128 * TSTRIDE)        // 18432 B per operand tile
#define STAGEB  (2 * TILEB)            // A + B
#define SM_MAIN_BYTES (NSTAGES * STAGEB)   // 110592 B  (x2 CTAs = 221184 <= 228KB)

#define SRC_BLKS 128                   // srcsum partial blocks (64 rows each)

// ---------------- device scratch (static: no runtime allocation) -----------
__device__ __nv_bfloat16 g_img_bf [NROWS * DDIM];   // scale * img, bf16
__device__ __nv_bfloat16 g_text_bf[NROWS * DDIM];
__device__ float g_Spart[SRC_BLKS * NSRC * DDIM];
__device__ float g_S[NSRC * DDIM];
__device__ int   g_cntPart[SRC_BLKS * NSRC];
__device__ int   g_cnt[NSRC];
__device__ float g_pmax[NROWS * NCHUNKS];
__device__ float g_psum[NROWS * NCHUNKS];
__device__ float g_ploss[1024];
__device__ int   g_done;               // static-init 0; reset by last block

// ---------------- label handling --------------------------------------------
// Warp-collective dtype detect: int64 labels in [0,8) have all odd 32-bit
// words zero; 32 random int32 labels all-zero has prob 8^-32. Deterministic.
__device__ __forceinline__ int detect_lab64_warp(const void* labels, int lane) {
    int w = ((const int*)labels)[2 * lane + 1];
    unsigned nb = __ballot_sync(0xffffffffu, w != 0);
    return nb == 0u;
}

__device__ __forceinline__ int get_label(const void* p, int i, int lab64) {
    int v = lab64 ? (int)((const long long*)p)[i] : ((const int*)p)[i];
    return (v < 0) ? 0 : (v >= NSRC ? NSRC - 1 : v);
}

// ---------------- PTX helpers ----------------------------------------------
__device__ __forceinline__ uint32_t smem_to_u32(const void* p) {
    uint32_t a;
    asm("{ .reg .u64 t; cvta.to.shared.u64 t, %1; cvt.u32.u64 %0, t; }"
        : "=r"(a) : "l"(p));
    return a;
}

#define CP_ASYNC16(saddr, gptr) \
    asm volatile("cp.async.cg.shared.global [%0], [%1], 16;" \
        :: "r"(saddr), "l"(gptr))
#define CP_COMMIT() asm volatile("cp.async.commit_group;")
#define CP_WAIT(n)  asm volatile("cp.async.wait_group %0;" :: "n"(n))

#define LDMATRIX_X4(r, addr) \
    asm volatile("ldmatrix.sync.aligned.m8n8.x4.shared.b16 {%0,%1,%2,%3}, [%4];" \
        : "=r"((r)[0]), "=r"((r)[1]), "=r"((r)[2]), "=r"((r)[3]) : "r"(addr))

#define MMA16816(d, a, b) \
    asm volatile("mma.sync.aligned.m16n8k16.row.col.f32.bf16.bf16.f32 " \
        "{%0,%1,%2,%3}, {%4,%5,%6,%7}, {%8,%9}, {%0,%1,%2,%3};" \
        : "+f"((d)[0]), "+f"((d)[1]), "+f"((d)[2]), "+f"((d)[3]) \
        : "r"((a)[0]), "r"((a)[1]), "r"((a)[2]), "r"((a)[3]), \
          "r"((b)[0]), "r"((b)[1]))

// ---------------- prologue kernels ------------------------------------------

// convert one tensor to bf16; destination selected IN DEVICE CODE (which:
// 0 = img (scaled), 1 = text). Never pass __device__ symbols from host.
__global__ void convert_kernel(const float* __restrict__ src,
                               const float* __restrict__ scale_ptr,
                               int which) {
    const int total4 = NROWS * DDIM / 4;
    int i = blockIdx.x * blockDim.x + threadIdx.x;
    if (i >= total4) return;
    __nv_bfloat16* dst = which ? g_text_bf : g_img_bf;
    float s = which ? 1.f : *scale_ptr;
    float4 v = ((const float4*)src)[i];
    __nv_bfloat162 lo = __floats2bfloat162_rn(s * v.x, s * v.y);
    __nv_bfloat162 hi = __floats2bfloat162_rn(s * v.z, s * v.w);
    ((uint2*)dst)[i] = make_uint2(*(uint32_t*)&lo, *(uint32_t*)&hi);
}

// per-64-row partial class sums of text features (128 blocks, coalesced)
__global__ void srcsum_kernel(const float* __restrict__ text,
                              const void* __restrict__ labels) {
    __shared__ int slab[64];
    __shared__ int s_is64;
    const int k = threadIdx.x;          // 512 threads, one feature column each
    const int r0 = blockIdx.x * 64;
    if (k < 32) {
        int is64 = detect_lab64_warp(labels, k);
        if (k == 0) s_is64 = is64;
    }
    __syncthreads();
    if (k < 64) slab[k] = get_label(labels, r0 + k, s_is64);
    __syncthreads();
    float s[NSRC];
#pragma unroll
    for (int c = 0; c < NSRC; c++) s[c] = 0.f;
    for (int r = 0; r < 64; r++) {
        int lab = slab[r];
        float v = text[(r0 + r) * DDIM + k];
#pragma unroll
        for (int c = 0; c < NSRC; c++) s[c] += (lab == c) ? v : 0.f;
    }
#pragma unroll
    for (int c = 0; c < NSRC; c++)
        g_Spart[(blockIdx.x * NSRC + c) * DDIM + k] = s[c];
    if (k < NSRC) {
        int cnt = 0;
        for (int r = 0; r < 64; r++) cnt += (slab[r] == k);
        g_cntPart[blockIdx.x * NSRC + k] = cnt;
    }
}

// fully-coalesced column sum: thread t owns output (blockIdx*256 + t),
// loops over the 128 partial blocks. Every warp load is one 128B line.
__global__ void reduceS_kernel() {
    const int out = blockIdx.x * 256 + threadIdx.x;   // 16 blocks x 256 = 4096
    float a = 0.f;
#pragma unroll 8
    for (int p = 0; p < SRC_BLKS; p++)
        a += g_Spart[p * (NSRC * DDIM) + out];
    g_S[out] = a;

    if (blockIdx.x == 0 && threadIdx.x < NSRC) {
        int c = 0;
        for (int p = 0; p < SRC_BLKS; p++)
            c += g_cntPart[p * NSRC + threadIdx.x];
        g_cnt[threadIdx.x] = c;
    }
}

// ---------------- main fused GEMM + online logsumexp ------------------------

// issue cp.async for one BK=64 k-slice (A + B tiles) into `stage`
__device__ __forceinline__ void load_tiles(uint32_t sb, int stage,
                                           int m0, int n0, int tid, int k0) {
#pragma unroll
    for (int i = 0; i < 8; i++) {
        int idx    = i * MAIN_THREADS + tid;  // 0..2047
        int tile   = idx >> 10;               // 0=A, 1=B
        int within = idx & 1023;
        int row    = within >> 3;             // 0..127
        int c8     = within & 7;              // 16B chunks
        const __nv_bfloat16* base = tile ? g_text_bf : g_img_bf;
        int grow = (tile ? n0 : m0) + row;
        const __nv_bfloat16* g = base + grow * DDIM + k0 + c8 * 8;
        uint32_t s = sb + stage * STAGEB + tile * TILEB + row * TSTRIDE + c8 * 16;
        CP_ASYNC16(s, g);
    }
}

// grid = 4096 CTAs: (mt 0..63) x (nt 0..63); each CTA: ONE 128x128 tile.
// 8 warps: wm 0..3 (32-row strip), wn 0..1 (64-col strip)
__global__ void __launch_bounds__(MAIN_THREADS, 2)
gemm_lse_kernel() {
    extern __shared__ char smem[];
    uint32_t sb = smem_to_u32(smem);
    const int tid  = threadIdx.x;
    const int warp = tid >> 5;
    const int lane = tid & 31;
    const int wm = warp >> 1;           // 0..3  (M subtile)
    const int wn = warp & 1;            // 0..1  (N subtile)
    const int mt = blockIdx.x & 63;
    const int nt = blockIdx.x >> 6;     // 0..63
    const int m0 = mt * BM;
    const int n0 = nt * BN;
    const float NEG_INF = __int_as_float(0xff800000);

    // ldmatrix per-lane address offsets (within an operand tile)
    const int a_row = wm * 32 + (lane & 15);                           // + tm*16
    const uint32_t a_off = (uint32_t)(a_row * TSTRIDE + ((lane >> 4) << 4));
    const int b_row = wn * 64 + (lane & 7) + (((lane >> 4) & 1) << 3); // + tn2*16
    const uint32_t b_off = (uint32_t)(b_row * TSTRIDE + (((lane >> 3) & 1) << 4));

    float acc[2][8][4];        // [tm][tn][q] — 64 regs
#pragma unroll
    for (int i = 0; i < 2; i++)
#pragma unroll
        for (int j = 0; j < 8; j++)
#pragma unroll
            for (int q = 0; q < 4; q++) acc[i][j][q] = 0.f;

    load_tiles(sb, 0, m0, n0, tid, 0);  CP_COMMIT();
    load_tiles(sb, 1, m0, n0, tid, BK); CP_COMMIT();

    for (int ks = 0; ks < KSTEPS; ks++) {
        CP_WAIT(1);            // stage ks resident
        __syncthreads();       // all warps finished compute(ks-1)
        if (ks + 2 < KSTEPS)
            load_tiles(sb, (ks + 2) % NSTAGES, m0, n0, tid, (ks + 2) * BK);
        CP_COMMIT();           // may be empty (keeps wait count uniform)

        const uint32_t tb = sb + (uint32_t)((ks % NSTAGES) * STAGEB);
#pragma unroll
        for (int ksub = 0; ksub < 4; ksub++) {
            const uint32_t koff = (uint32_t)(ksub * 32);  // 16 elems = 32 B
            uint32_t afrag[2][4];
#pragma unroll
            for (int tm = 0; tm < 2; tm++) {
                uint32_t addr = tb + a_off + (uint32_t)(tm * 16 * TSTRIDE) + koff;
                LDMATRIX_X4(afrag[tm], addr);
            }
            uint32_t bfrag[8][2];
#pragma unroll
            for (int tn2 = 0; tn2 < 4; tn2++) {
                uint32_t addr = tb + TILEB + b_off
                              + (uint32_t)(tn2 * 16 * TSTRIDE) + koff;
                uint32_t r[4];
                LDMATRIX_X4(r, addr);
                bfrag[2 * tn2][0] = r[0];     bfrag[2 * tn2][1] = r[1];
                bfrag[2 * tn2 + 1][0] = r[2]; bfrag[2 * tn2 + 1][1] = r[3];
            }
#pragma unroll
            for (int tm = 0; tm < 2; tm++)
#pragma unroll
                for (int tn = 0; tn < 8; tn++)
                    MMA16816(acc[tm][tn], afrag[tm], bfrag[tn]);
        }
    }

    // one-shot epilogue: per-row max/sumexp over this 128-col tile
    float rm[2][2], rs[2][2];
#pragma unroll
    for (int tm = 0; tm < 2; tm++) {
#pragma unroll
        for (int half = 0; half < 2; half++) {
            float mx = NEG_INF;
#pragma unroll
            for (int tn = 0; tn < 8; tn++)
                mx = fmaxf(mx, fmaxf(acc[tm][tn][half * 2],
                                     acc[tm][tn][half * 2 + 1]));
            mx = fmaxf(mx, __shfl_xor_sync(0xffffffffu, mx, 1));
            mx = fmaxf(mx, __shfl_xor_sync(0xffffffffu, mx, 2));
            float s = 0.f;
#pragma unroll
            for (int tn = 0; tn < 8; tn++) {
                s += __expf(acc[tm][tn][half * 2]     - mx);
                s += __expf(acc[tm][tn][half * 2 + 1] - mx);
            }
            s += __shfl_xor_sync(0xffffffffu, s, 1);
            s += __shfl_xor_sync(0xffffffffu, s, 2);
            rm[tm][half] = mx;
            rs[tm][half] = s;
        }
    }

    // merge the two N-warps (wn=0/1) per row and store tile partials
    float* s_m = (float*)smem;            // [2][128] (reuse tile smem)
    float* s_s = s_m + 256;
    __syncthreads();
    if ((lane & 3) == 0) {
#pragma unroll
        for (int tm = 0; tm < 2; tm++)
#pragma unroll
            for (int half = 0; half < 2; half++) {
                int row = wm * 32 + tm * 16 + half * 8 + (lane >> 2);
                s_m[wn * 128 + row] = rm[tm][half];
                s_s[wn * 128 + row] = rs[tm][half];
            }
    }
    __syncthreads();
    if (tid < BM) {
        float ma = s_m[tid], mb = s_m[128 + tid];
        float M = fmaxf(ma, mb);
        float S = s_s[tid] * __expf(ma - M) + s_s[128 + tid] * __expf(mb - M);
        g_pmax[(m0 + tid) * NCHUNKS + nt] = M;
        g_psum[(m0 + tid) * NCHUNKS + nt] = S;
    }
}

// ---------------- per-row finalize + last-block final reduce ----------------
__global__ void finalize_rows(const float* __restrict__ img,
                              const float* __restrict__ text,
                              const void* __restrict__ labels,
                              const float* __restrict__ scale_ptr,
                              float* __restrict__ out) {
    __shared__ int s_is64;
    __shared__ float sh[8];
    __shared__ int s_last;
    __shared__ float red[256];

    const int warp = threadIdx.x >> 5;
    const int lane = threadIdx.x & 31;
    const int row  = blockIdx.x * 8 + warp;
    const float scale = *scale_ptr;

    if (threadIdx.x < 32) {
        int is64 = detect_lab64_warp(labels, lane);
        if (lane == 0) s_is64 = is64;
    }
    __syncthreads();

    const int c = get_label(labels, row, s_is64);
    const int cnt = g_cnt[c] - 1;

    // combine 64 logsumexp partials: 2 entries per lane
    float pm0 = g_pmax[row * NCHUNKS + lane];
    float pm1 = g_pmax[row * NCHUNKS + 32 + lane];
    float M = fmaxf(pm0, pm1);
#pragma unroll
    for (int o = 16; o; o >>= 1) M = fmaxf(M, __shfl_xor_sync(0xffffffffu, M, o));
    float ps = g_psum[row * NCHUNKS + lane] * __expf(pm0 - M)
             + g_psum[row * NCHUNKS + 32 + lane] * __expf(pm1 - M);
#pragma unroll
    for (int o = 16; o; o >>= 1) ps += __shfl_xor_sync(0xffffffffu, ps, o);
    float lse = M + __logf(ps);

    // exact fp32 masked-sum dot: img_row · (S_c - text_row), float4 loads
    const float4* img4  = (const float4*)(img  + row * DDIM);
    const float4* txt4  = (const float4*)(text + row * DDIM);
    const float4* Sc4   = (const float4*)(g_S + c * DDIM);
    float d = 0.f;
#pragma unroll
    for (int g = 0; g < DDIM / 128; g++) {
        int k = g * 32 + lane;
        float4 a = img4[k], b = txt4[k], s4 = Sc4[k];
        d += a.x * (s4.x - b.x) + a.y * (s4.y - b.y)
           + a.z * (s4.z - b.z) + a.w * (s4.w - b.w);
    }
#pragma unroll
    for (int o = 16; o; o >>= 1) d += __shfl_xor_sync(0xffffffffu, d, o);

    if (lane == 0)
        sh[warp] = (cnt > 0) ? (scale * d - (float)cnt * lse) / (float)cnt : 0.f;
    __syncthreads();
    if (threadIdx.x == 0) {
        float a = 0.f;
#pragma unroll
        for (int w = 0; w < 8; w++) a += sh[w];
        g_ploss[blockIdx.x] = a;
        __threadfence();
        int old = atomicAdd(&g_done, 1);
        s_last = (old == 1023);
    }
    __syncthreads();

    // last block: deterministic final reduction of the 1024 partials
    if (s_last) {
        __threadfence();
        float a = 0.f;
        for (int i = threadIdx.x; i < 1024; i += 256) a += g_ploss[i];
        red[threadIdx.x] = a;
        __syncthreads();
        for (int s = 128; s; s >>= 1) {
            if (threadIdx.x < s) red[threadIdx.x] += red[threadIdx.x + s];
            __syncthreads();
        }
        if (threadIdx.x == 0) {
            out[0] = -red[0] / (float)NROWS;
            g_done = 0;                    // reset for next graph replay
        }
    }
}

// ---------------- launch ----------------------------------------------------
extern "C" void kernel_launch(void* const* d_in, const int* in_sizes, int n_in,
                              void* d_out, int out_size) {
    // Identify inputs by element count (robust to metadata ordering).
    const float* img   = nullptr;
    const float* text  = nullptr;
    const float* scale = nullptr;
    const void*  labels = nullptr;
    for (int i = 0; i < n_in; i++) {
        int s = in_sizes[i];
        if (s == NROWS * DDIM) {
            if (!img) img = (const float*)d_in[i];
            else      text = (const float*)d_in[i];
        } else if (s == 1) {
            scale = (const float*)d_in[i];
        } else if (s == NROWS) {
            labels = d_in[i];
        }
    }
    float* out = (float*)d_out;

    cudaFuncSetAttribute(gemm_lse_kernel,
                         cudaFuncAttributeMaxDynamicSharedMemorySize, SM_MAIN_BYTES);

    // 6 launches; gemm stays at capture slot 3.
    const int conv_blocks = (NROWS * DDIM / 4 + 255) / 256;
    convert_kernel<<<conv_blocks, 256>>>(img,  scale, 0);            // 0
    convert_kernel<<<conv_blocks, 256>>>(text, scale, 1);            // 1
    srcsum_kernel<<<SRC_BLKS, 512>>>(text, labels);                  // 2
    gemm_lse_kernel<<<4096, MAIN_THREADS, SM_MAIN_BYTES>>>();        // 3
    reduceS_kernel<<<16, 256>>>();                                   // 4
    finalize_rows<<<1024, 256>>>(img, text, labels, scale, out);     // 5
}

// round 15
// speedup vs baseline: 1.0296x; 1.0097x over previous
#include <cuda_runtime.h>
#include <cuda_bf16.h>
#include <cstdint>

// ============================================================================
// SourceAwareContrastiveLoss, GB300 — base sm_103 ISA.
// R15: tail fusion — text convert + srcsum share one kernel (one 16MB fp32
// read instead of two); 5 launches. GEMM = R14 (4096 CTAs, 2 CTA/SM, 8-warp
// bf16 mma.sync, ~192us ≈ legacy-HMMA pipe floor on this die).
//
// loss = -(1/N) sum_i (scale*img_i·(S_{c(i)} - text_i) - cnt_i*lse_i)/cnt_i
// lse_i = logsumexp_j scale*(img_i·text_j)
// ============================================================================

#define NROWS 8192
#define DDIM  512
#define NSRC  8
#define BM    128
#define BN    128
#define BK    64
#define KSTEPS (DDIM / BK)     // 8 K-steps per tile
#define NCHUNKS 64             // one partial per 128-column tile
#define MAIN_THREADS 256
#define NSTAGES 3

#define TSTRIDE 144                    // 128 B data + 16 B pad (conflict-free ldmatrix)
#define TILEB   (128 * TSTRIDE)        // 18432 B per operand tile
#define STAGEB  (2 * TILEB)            // A + B
#define SM_MAIN_BYTES (NSTAGES * STAGEB)   // 110592 B  (x2 CTAs = 221184 <= 228KB)

#define SRC_BLKS 128                   // srcsum partial blocks (64 rows each)

// ---------------- device scratch (static: no runtime allocation) -----------
__device__ __nv_bfloat16 g_img_bf [NROWS * DDIM];   // scale * img, bf16
__device__ __nv_bfloat16 g_text_bf[NROWS * DDIM];
__device__ float g_Spart[SRC_BLKS * NSRC * DDIM];
__device__ float g_S[NSRC * DDIM];
__device__ int   g_cntPart[SRC_BLKS * NSRC];
__device__ int   g_cnt[NSRC];
__device__ float g_pmax[NROWS * NCHUNKS];
__device__ float g_psum[NROWS * NCHUNKS];
__device__ float g_ploss[1024];
__device__ int   g_done;               // static-init 0; reset by last block

// ---------------- label handling --------------------------------------------
// Warp-collective dtype detect: int64 labels in [0,8) have all odd 32-bit
// words zero; 32 random int32 labels all-zero has prob 8^-32. Deterministic.
__device__ __forceinline__ int detect_lab64_warp(const void* labels, int lane) {
    int w = ((const int*)labels)[2 * lane + 1];
    unsigned nb = __ballot_sync(0xffffffffu, w != 0);
    return nb == 0u;
}

__device__ __forceinline__ int get_label(const void* p, int i, int lab64) {
    int v = lab64 ? (int)((const long long*)p)[i] : ((const int*)p)[i];
    return (v < 0) ? 0 : (v >= NSRC ? NSRC - 1 : v);
}

// ---------------- PTX helpers ----------------------------------------------
__device__ __forceinline__ uint32_t smem_to_u32(const void* p) {
    uint32_t a;
    asm("{ .reg .u64 t; cvta.to.shared.u64 t, %1; cvt.u32.u64 %0, t; }"
        : "=r"(a) : "l"(p));
    return a;
}

#define CP_ASYNC16(saddr, gptr) \
    asm volatile("cp.async.cg.shared.global [%0], [%1], 16;" \
        :: "r"(saddr), "l"(gptr))
#define CP_COMMIT() asm volatile("cp.async.commit_group;")
#define CP_WAIT(n)  asm volatile("cp.async.wait_group %0;" :: "n"(n))

#define LDMATRIX_X4(r, addr) \
    asm volatile("ldmatrix.sync.aligned.m8n8.x4.shared.b16 {%0,%1,%2,%3}, [%4];" \
        : "=r"((r)[0]), "=r"((r)[1]), "=r"((r)[2]), "=r"((r)[3]) : "r"(addr))

#define MMA16816(d, a, b) \
    asm volatile("mma.sync.aligned.m16n8k16.row.col.f32.bf16.bf16.f32 " \
        "{%0,%1,%2,%3}, {%4,%5,%6,%7}, {%8,%9}, {%0,%1,%2,%3};" \
        : "+f"((d)[0]), "+f"((d)[1]), "+f"((d)[2]), "+f"((d)[3]) \
        : "r"((a)[0]), "r"((a)[1]), "r"((a)[2]), "r"((a)[3]), \
          "r"((b)[0]), "r"((b)[1]))

// ---------------- prologue kernels ------------------------------------------

// convert img to scaled bf16 (float4-vectorized); dst chosen in device code.
__global__ void convert_img_kernel(const float* __restrict__ src,
                                   const float* __restrict__ scale_ptr) {
    const int total4 = NROWS * DDIM / 4;
    int i = blockIdx.x * blockDim.x + threadIdx.x;
    if (i >= total4) return;
    float s = *scale_ptr;
    float4 v = ((const float4*)src)[i];
    __nv_bfloat162 lo = __floats2bfloat162_rn(s * v.x, s * v.y);
    __nv_bfloat162 hi = __floats2bfloat162_rn(s * v.z, s * v.w);
    ((uint2*)g_img_bf)[i] = make_uint2(*(uint32_t*)&lo, *(uint32_t*)&hi);
}

// FUSED: convert text to bf16 AND accumulate per-64-row class partial sums.
// One 16MB fp32 read serves both consumers. 128 blocks x 512 threads; thread
// owns feature column k; loops over the block's 64 rows.
__global__ void conv_text_srcsum_kernel(const float* __restrict__ text,
                                        const void* __restrict__ labels) {
    __shared__ int slab[64];
    __shared__ int s_is64;
    const int k = threadIdx.x;          // 0..511, one feature column
    const int r0 = blockIdx.x * 64;
    if (k < 32) {
        int is64 = detect_lab64_warp(labels, k);
        if (k == 0) s_is64 = is64;
    }
    __syncthreads();
    if (k < 64) slab[k] = get_label(labels, r0 + k, s_is64);
    __syncthreads();
    float s[NSRC];
#pragma unroll
    for (int c = 0; c < NSRC; c++) s[c] = 0.f;
    for (int r = 0; r < 64; r++) {
        int lab = slab[r];
        int idx = (r0 + r) * DDIM + k;
        float v = text[idx];                         // coalesced 2KB/row
        g_text_bf[idx] = __float2bfloat16(v);        // fused convert
#pragma unroll
        for (int c = 0; c < NSRC; c++) s[c] += (lab == c) ? v : 0.f;
    }
#pragma unroll
    for (int c = 0; c < NSRC; c++)
        g_Spart[(blockIdx.x * NSRC + c) * DDIM + k] = s[c];
    if (k < NSRC) {
        int cnt = 0;
        for (int r = 0; r < 64; r++) cnt += (slab[r] == k);
        g_cntPart[blockIdx.x * NSRC + k] = cnt;
    }
}

// fully-coalesced column sum: thread t owns output (blockIdx*256 + t),
// loops over the 128 partial blocks. Every warp load is one 128B line.
__global__ void reduceS_kernel() {
    const int out = blockIdx.x * 256 + threadIdx.x;   // 16 blocks x 256 = 4096
    float a = 0.f;
#pragma unroll 8
    for (int p = 0; p < SRC_BLKS; p++)
        a += g_Spart[p * (NSRC * DDIM) + out];
    g_S[out] = a;

    if (blockIdx.x == 0 && threadIdx.x < NSRC) {
        int c = 0;
        for (int p = 0; p < SRC_BLKS; p++)
            c += g_cntPart[p * NSRC + threadIdx.x];
        g_cnt[threadIdx.x] = c;
    }
}

// ---------------- main fused GEMM + online logsumexp ------------------------

// issue cp.async for one BK=64 k-slice (A + B tiles) into `stage`
__device__ __forceinline__ void load_tiles(uint32_t sb, int stage,
                                           int m0, int n0, int tid, int k0) {
#pragma unroll
    for (int i = 0; i < 8; i++) {
        int idx    = i * MAIN_THREADS + tid;  // 0..2047
        int tile   = idx >> 10;               // 0=A, 1=B
        int within = idx & 1023;
        int row    = within >> 3;             // 0..127
        int c8     = within & 7;              // 16B chunks
        const __nv_bfloat16* base = tile ? g_text_bf : g_img_bf;
        int grow = (tile ? n0 : m0) + row;
        const __nv_bfloat16* g = base + grow * DDIM + k0 + c8 * 8;
        uint32_t s = sb + stage * STAGEB + tile * TILEB + row * TSTRIDE + c8 * 16;
        CP_ASYNC16(s, g);
    }
}

// grid = 4096 CTAs: (mt 0..63) x (nt 0..63); each CTA: ONE 128x128 tile.
// 8 warps: wm 0..3 (32-row strip), wn 0..1 (64-col strip)
__global__ void __launch_bounds__(MAIN_THREADS, 2)
gemm_lse_kernel() {
    extern __shared__ char smem[];
    uint32_t sb = smem_to_u32(smem);
    const int tid  = threadIdx.x;
    const int warp = tid >> 5;
    const int lane = tid & 31;
    const int wm = warp >> 1;           // 0..3  (M subtile)
    const int wn = warp & 1;            // 0..1  (N subtile)
    const int mt = blockIdx.x & 63;
    const int nt = blockIdx.x >> 6;     // 0..63
    const int m0 = mt * BM;
    const int n0 = nt * BN;
    const float NEG_INF = __int_as_float(0xff800000);

    // ldmatrix per-lane address offsets (within an operand tile)
    const int a_row = wm * 32 + (lane & 15);                           // + tm*16
    const uint32_t a_off = (uint32_t)(a_row * TSTRIDE + ((lane >> 4) << 4));
    const int b_row = wn * 64 + (lane & 7) + (((lane >> 4) & 1) << 3); // + tn2*16
    const uint32_t b_off = (uint32_t)(b_row * TSTRIDE + (((lane >> 3) & 1) << 4));

    float acc[2][8][4];        // [tm][tn][q] — 64 regs
#pragma unroll
    for (int i = 0; i < 2; i++)
#pragma unroll
        for (int j = 0; j < 8; j++)
#pragma unroll
            for (int q = 0; q < 4; q++) acc[i][j][q] = 0.f;

    load_tiles(sb, 0, m0, n0, tid, 0);  CP_COMMIT();
    load_tiles(sb, 1, m0, n0, tid, BK); CP_COMMIT();

    for (int ks = 0; ks < KSTEPS; ks++) {
        CP_WAIT(1);            // stage ks resident
        __syncthreads();       // all warps finished compute(ks-1)
        if (ks + 2 < KSTEPS)
            load_tiles(sb, (ks + 2) % NSTAGES, m0, n0, tid, (ks + 2) * BK);
        CP_COMMIT();           // may be empty (keeps wait count uniform)

        const uint32_t tb = sb + (uint32_t)((ks % NSTAGES) * STAGEB);
#pragma unroll
        for (int ksub = 0; ksub < 4; ksub++) {
            const uint32_t koff = (uint32_t)(ksub * 32);  // 16 elems = 32 B
            uint32_t afrag[2][4];
#pragma unroll
            for (int tm = 0; tm < 2; tm++) {
                uint32_t addr = tb + a_off + (uint32_t)(tm * 16 * TSTRIDE) + koff;
                LDMATRIX_X4(afrag[tm], addr);
            }
            uint32_t bfrag[8][2];
#pragma unroll
            for (int tn2 = 0; tn2 < 4; tn2++) {
                uint32_t addr = tb + TILEB + b_off
                              + (uint32_t)(tn2 * 16 * TSTRIDE) + koff;
                uint32_t r[4];
                LDMATRIX_X4(r, addr);
                bfrag[2 * tn2][0] = r[0];     bfrag[2 * tn2][1] = r[1];
                bfrag[2 * tn2 + 1][0] = r[2]; bfrag[2 * tn2 + 1][1] = r[3];
            }
#pragma unroll
            for (int tm = 0; tm < 2; tm++)
#pragma unroll
                for (int tn = 0; tn < 8; tn++)
                    MMA16816(acc[tm][tn], afrag[tm], bfrag[tn]);
        }
    }

    // one-shot epilogue: per-row max/sumexp over this 128-col tile
    float rm[2][2], rs[2][2];
#pragma unroll
    for (int tm = 0; tm < 2; tm++) {
#pragma unroll
        for (int half = 0; half < 2; half++) {
            float mx = NEG_INF;
#pragma unroll
            for (int tn = 0; tn < 8; tn++)
                mx = fmaxf(mx, fmaxf(acc[tm][tn][half * 2],
                                     acc[tm][tn][half * 2 + 1]));
            mx = fmaxf(mx, __shfl_xor_sync(0xffffffffu, mx, 1));
            mx = fmaxf(mx, __shfl_xor_sync(0xffffffffu, mx, 2));
            float s = 0.f;
#pragma unroll
            for (int tn = 0; tn < 8; tn++) {
                s += __expf(acc[tm][tn][half * 2]     - mx);
                s += __expf(acc[tm][tn][half * 2 + 1] - mx);
            }
            s += __shfl_xor_sync(0xffffffffu, s, 1);
            s += __shfl_xor_sync(0xffffffffu, s, 2);
            rm[tm][half] = mx;
            rs[tm][half] = s;
        }
    }

    // merge the two N-warps (wn=0/1) per row and store tile partials
    float* s_m = (float*)smem;            // [2][128] (reuse tile smem)
    float* s_s = s_m + 256;
    __syncthreads();
    if ((lane & 3) == 0) {
#pragma unroll
        for (int tm = 0; tm < 2; tm++)
#pragma unroll
            for (int half = 0; half < 2; half++) {
                int row = wm * 32 + tm * 16 + half * 8 + (lane >> 2);
                s_m[wn * 128 + row] = rm[tm][half];
                s_s[wn * 128 + row] = rs[tm][half];
            }
    }
    __syncthreads();
    if (tid < BM) {
        float ma = s_m[tid], mb = s_m[128 + tid];
        float M = fmaxf(ma, mb);
        float S = s_s[tid] * __expf(ma - M) + s_s[128 + tid] * __expf(mb - M);
        g_pmax[(m0 + tid) * NCHUNKS + nt] = M;
        g_psum[(m0 + tid) * NCHUNKS + nt] = S;
    }
}

// ---------------- per-row finalize + last-block final reduce ----------------
__global__ void finalize_rows(const float* __restrict__ img,
                              const float* __restrict__ text,
                              const void* __restrict__ labels,
                              const float* __restrict__ scale_ptr,
                              float* __restrict__ out) {
    __shared__ int s_is64;
    __shared__ float sh[8];
    __shared__ int s_last;
    __shared__ float red[256];

    const int warp = threadIdx.x >> 5;
    const int lane = threadIdx.x & 31;
    const int row  = blockIdx.x * 8 + warp;
    const float scale = *scale_ptr;

    if (threadIdx.x < 32) {
        int is64 = detect_lab64_warp(labels, lane);
        if (lane == 0) s_is64 = is64;
    }
    __syncthreads();

    const int c = get_label(labels, row, s_is64);
    const int cnt = g_cnt[c] - 1;

    // combine 64 logsumexp partials: 2 entries per lane
    float pm0 = g_pmax[row * NCHUNKS + lane];
    float pm1 = g_pmax[row * NCHUNKS + 32 + lane];
    float M = fmaxf(pm0, pm1);
#pragma unroll
    for (int o = 16; o; o >>= 1) M = fmaxf(M, __shfl_xor_sync(0xffffffffu, M, o));
    float ps = g_psum[row * NCHUNKS + lane] * __expf(pm0 - M)
             + g_psum[row * NCHUNKS + 32 + lane] * __expf(pm1 - M);
#pragma unroll
    for (int o = 16; o; o >>= 1) ps += __shfl_xor_sync(0xffffffffu, ps, o);
    float lse = M + __logf(ps);

    // exact fp32 masked-sum dot: img_row · (S_c - text_row), float4 loads
    const float4* img4  = (const float4*)(img  + row * DDIM);
    const float4* txt4  = (const float4*)(text + row * DDIM);
    const float4* Sc4   = (const float4*)(g_S + c * DDIM);
    float d = 0.f;
#pragma unroll
    for (int g = 0; g < DDIM / 128; g++) {
        int k = g * 32 + lane;
        float4 a = img4[k], b = txt4[k], s4 = Sc4[k];
        d += a.x * (s4.x - b.x) + a.y * (s4.y - b.y)
           + a.z * (s4.z - b.z) + a.w * (s4.w - b.w);
    }
#pragma unroll
    for (int o = 16; o; o >>= 1) d += __shfl_xor_sync(0xffffffffu, d, o);

    if (lane == 0)
        sh[warp] = (cnt > 0) ? (scale * d - (float)cnt * lse) / (float)cnt : 0.f;
    __syncthreads();
    if (threadIdx.x == 0) {
        float a = 0.f;
#pragma unroll
        for (int w = 0; w < 8; w++) a += sh[w];
        g_ploss[blockIdx.x] = a;
        __threadfence();
        int old = atomicAdd(&g_done, 1);
        s_last = (old == 1023);
    }
    __syncthreads();

    // last block: deterministic final reduction of the 1024 partials
    if (s_last) {
        __threadfence();
        float a = 0.f;
        for (int i = threadIdx.x; i < 1024; i += 256) a += g_ploss[i];
        red[threadIdx.x] = a;
        __syncthreads();
        for (int s = 128; s; s >>= 1) {
            if (threadIdx.x < s) red[threadIdx.x] += red[threadIdx.x + s];
            __syncthreads();
        }
        if (threadIdx.x == 0) {
            out[0] = -red[0] / (float)NROWS;
            g_done = 0;                    // reset for next graph replay
        }
    }
}

// ---------------- launch ----------------------------------------------------
extern "C" void kernel_launch(void* const* d_in, const int* in_sizes, int n_in,
                              void* d_out, int out_size) {
    // Identify inputs by element count (robust to metadata ordering).
    const float* img   = nullptr;
    const float* text  = nullptr;
    const float* scale = nullptr;
    const void*  labels = nullptr;
    for (int i = 0; i < n_in; i++) {
        int s = in_sizes[i];
        if (s == NROWS * DDIM) {
            if (!img) img = (const float*)d_in[i];
            else      text = (const float*)d_in[i];
        } else if (s == 1) {
            scale = (const float*)d_in[i];
        } else if (s == NROWS) {
            labels = d_in[i];
        }
    }
    float* out = (float*)d_out;

    cudaFuncSetAttribute(gemm_lse_kernel,
                         cudaFuncAttributeMaxDynamicSharedMemorySize, SM_MAIN_BYTES);

    // 5 launches; gemm stays at capture slot 3.
    const int conv_blocks = (NROWS * DDIM / 4 + 255) / 256;
    convert_img_kernel<<<conv_blocks, 256>>>(img, scale);            // 0
    conv_text_srcsum_kernel<<<SRC_BLKS, 512>>>(text, labels);        // 1
    reduceS_kernel<<<16, 256>>>();                                   // 2
    gemm_lse_kernel<<<4096, MAIN_THREADS, SM_MAIN_BYTES>>>();        // 3
    finalize_rows<<<1024, 256>>>(img, text, labels, scale, out);     // 4
}

// round 16
// speedup vs baseline: 1.0485x; 1.0183x over previous
#include <cuda_runtime.h>
#include <cuda_bf16.h>
#include <cstdint>

// ============================================================================
// SourceAwareContrastiveLoss, GB300 — base sm_103 ISA.
// R16: tail parallelization — ONE prologue kernel (role-split blocks: img
// convert runs CONCURRENTLY with text convert+srcsum); reduceS absorbed into
// the GEMM's first wave (CTAs 0..15, hidden by the other 280 first-wave
// CTAs). 3 launches total. GEMM mainloop = R14/R15 (pinned at the legacy
// HMMA issue floor, ~192us).
//
// loss = -(1/N) sum_i (scale*img_i·(S_{c(i)} - text_i) - cnt_i*lse_i)/cnt_i
// lse_i = logsumexp_j scale*(img_i·text_j)
// ============================================================================

#define NROWS 8192
#define DDIM  512
#define NSRC  8
#define BM    128
#define BN    128
#define BK    64
#define KSTEPS (DDIM / BK)     // 8 K-steps per tile
#define NCHUNKS 64             // one partial per 128-column tile
#define MAIN_THREADS 256
#define NSTAGES 3

#define TSTRIDE 144                    // 128 B data + 16 B pad (conflict-free ldmatrix)
#define TILEB   (128 * TSTRIDE)        // 18432 B per operand tile
#define STAGEB  (2 * TILEB)            // A + B
#define SM_MAIN_BYTES (NSTAGES * STAGEB)   // 110592 B  (x2 CTAs = 221184 <= 228KB)

#define SRC_BLKS 128                   // srcsum partial blocks (64 rows each)
#define IMG_BLOCKS 384                 // img-convert blocks in the fused prologue

// ---------------- device scratch (static: no runtime allocation) -----------
__device__ __nv_bfloat16 g_img_bf [NROWS * DDIM];   // scale * img, bf16
__device__ __nv_bfloat16 g_text_bf[NROWS * DDIM];
__device__ float g_Spart[SRC_BLKS * NSRC * DDIM];
__device__ float g_S[NSRC * DDIM];
__device__ int   g_cntPart[SRC_BLKS * NSRC];
__device__ int   g_cnt[NSRC];
__device__ float g_pmax[NROWS * NCHUNKS];
__device__ float g_psum[NROWS * NCHUNKS];
__device__ float g_ploss[1024];
__device__ int   g_done;               // static-init 0; reset by last block

// ---------------- label handling --------------------------------------------
// Warp-collective dtype detect: int64 labels in [0,8) have all odd 32-bit
// words zero; 32 random int32 labels all-zero has prob 8^-32. Deterministic.
__device__ __forceinline__ int detect_lab64_warp(const void* labels, int lane) {
    int w = ((const int*)labels)[2 * lane + 1];
    unsigned nb = __ballot_sync(0xffffffffu, w != 0);
    return nb == 0u;
}

__device__ __forceinline__ int get_label(const void* p, int i, int lab64) {
    int v = lab64 ? (int)((const long long*)p)[i] : ((const int*)p)[i];
    return (v < 0) ? 0 : (v >= NSRC ? NSRC - 1 : v);
}

// ---------------- PTX helpers ----------------------------------------------
__device__ __forceinline__ uint32_t smem_to_u32(const void* p) {
    uint32_t a;
    asm("{ .reg .u64 t; cvta.to.shared.u64 t, %1; cvt.u32.u64 %0, t; }"
        : "=r"(a) : "l"(p));
    return a;
}

#define CP_ASYNC16(saddr, gptr) \
    asm volatile("cp.async.cg.shared.global [%0], [%1], 16;" \
        :: "r"(saddr), "l"(gptr))
#define CP_COMMIT() asm volatile("cp.async.commit_group;")
#define CP_WAIT(n)  asm volatile("cp.async.wait_group %0;" :: "n"(n))

#define LDMATRIX_X4(r, addr) \
    asm volatile("ldmatrix.sync.aligned.m8n8.x4.shared.b16 {%0,%1,%2,%3}, [%4];" \
        : "=r"((r)[0]), "=r"((r)[1]), "=r"((r)[2]), "=r"((r)[3]) : "r"(addr))

#define MMA16816(d, a, b) \
    asm volatile("mma.sync.aligned.m16n8k16.row.col.f32.bf16.bf16.f32 " \
        "{%0,%1,%2,%3}, {%4,%5,%6,%7}, {%8,%9}, {%0,%1,%2,%3};" \
        : "+f"((d)[0]), "+f"((d)[1]), "+f"((d)[2]), "+f"((d)[3]) \
        : "r"((a)[0]), "r"((a)[1]), "r"((a)[2]), "r"((a)[3]), \
          "r"((b)[0]), "r"((b)[1]))

// ---------------- fused prologue --------------------------------------------
// blocks [0, SRC_BLKS): text convert + per-64-row class partial sums
// blocks [SRC_BLKS, SRC_BLKS+IMG_BLOCKS): img convert (scaled), grid-stride
// Both roles are data-independent and run concurrently.
__global__ void prologue_kernel(const float* __restrict__ img,
                                const float* __restrict__ text,
                                const void* __restrict__ labels,
                                const float* __restrict__ scale_ptr) {
    if (blockIdx.x < SRC_BLKS) {
        // ---- text convert + srcsum ----
        __shared__ int slab[64];
        __shared__ int s_is64;
        const int k = threadIdx.x;          // 0..511, one feature column
        const int r0 = blockIdx.x * 64;
        if (k < 32) {
            int is64 = detect_lab64_warp(labels, k);
            if (k == 0) s_is64 = is64;
        }
        __syncthreads();
        if (k < 64) slab[k] = get_label(labels, r0 + k, s_is64);
        __syncthreads();
        float s[NSRC];
#pragma unroll
        for (int c = 0; c < NSRC; c++) s[c] = 0.f;
        for (int r = 0; r < 64; r++) {
            int lab = slab[r];
            int idx = (r0 + r) * DDIM + k;
            float v = text[idx];                         // coalesced 2KB/row
            g_text_bf[idx] = __float2bfloat16(v);        // fused convert
#pragma unroll
            for (int c = 0; c < NSRC; c++) s[c] += (lab == c) ? v : 0.f;
        }
#pragma unroll
        for (int c = 0; c < NSRC; c++)
            g_Spart[(blockIdx.x * NSRC + c) * DDIM + k] = s[c];
        if (k < NSRC) {
            int cnt = 0;
            for (int r = 0; r < 64; r++) cnt += (slab[r] == k);
            g_cntPart[blockIdx.x * NSRC + k] = cnt;
        }
    } else {
        // ---- img convert (scaled), float4 grid-stride ----
        const int total4 = NROWS * DDIM / 4;
        const int stride = IMG_BLOCKS * 512;
        const float sc = *scale_ptr;
        for (int i = (blockIdx.x - SRC_BLKS) * 512 + threadIdx.x;
             i < total4; i += stride) {
            float4 v = ((const float4*)img)[i];
            __nv_bfloat162 lo = __floats2bfloat162_rn(sc * v.x, sc * v.y);
            __nv_bfloat162 hi = __floats2bfloat162_rn(sc * v.z, sc * v.w);
            ((uint2*)g_img_bf)[i] = make_uint2(*(uint32_t*)&lo, *(uint32_t*)&hi);
        }
    }
}

// ---------------- main fused GEMM + online logsumexp ------------------------

// issue cp.async for one BK=64 k-slice (A + B tiles) into `stage`
__device__ __forceinline__ void load_tiles(uint32_t sb, int stage,
                                           int m0, int n0, int tid, int k0) {
#pragma unroll
    for (int i = 0; i < 8; i++) {
        int idx    = i * MAIN_THREADS + tid;  // 0..2047
        int tile   = idx >> 10;               // 0=A, 1=B
        int within = idx & 1023;
        int row    = within >> 3;             // 0..127
        int c8     = within & 7;              // 16B chunks
        const __nv_bfloat16* base = tile ? g_text_bf : g_img_bf;
        int grow = (tile ? n0 : m0) + row;
        const __nv_bfloat16* g = base + grow * DDIM + k0 + c8 * 8;
        uint32_t s = sb + stage * STAGEB + tile * TILEB + row * TSTRIDE + c8 * 16;
        CP_ASYNC16(s, g);
    }
}

// grid = 4096 CTAs: (mt 0..63) x (nt 0..63); each CTA: ONE 128x128 tile.
// 8 warps: wm 0..3 (32-row strip), wn 0..1 (64-col strip)
// CTAs 0..15 additionally perform the coalesced reduceS before their tile
// (srcsum completed in the previous launch; g_S is read only by finalize).
__global__ void __launch_bounds__(MAIN_THREADS, 2)
gemm_lse_kernel() {
    extern __shared__ char smem[];
    uint32_t sb = smem_to_u32(smem);
    const int tid  = threadIdx.x;
    const int warp = tid >> 5;
    const int lane = tid & 31;
    const int wm = warp >> 1;           // 0..3  (M subtile)
    const int wn = warp & 1;            // 0..1  (N subtile)
    const int mt = blockIdx.x & 63;
    const int nt = blockIdx.x >> 6;     // 0..63
    const int m0 = mt * BM;
    const int n0 = nt * BN;
    const float NEG_INF = __int_as_float(0xff800000);

    // absorbed reduceS: 16 CTAs x 256 threads = 4096 outputs, coalesced
    if (blockIdx.x < 16) {
        int out = blockIdx.x * 256 + tid;
        float a = 0.f;
#pragma unroll 8
        for (int p = 0; p < SRC_BLKS; p++)
            a += g_Spart[p * (NSRC * DDIM) + out];
        g_S[out] = a;
        if (blockIdx.x == 0 && tid < NSRC) {
            int c = 0;
            for (int p = 0; p < SRC_BLKS; p++)
                c += g_cntPart[p * NSRC + tid];
            g_cnt[tid] = c;
        }
    }

    // ldmatrix per-lane address offsets (within an operand tile)
    const int a_row = wm * 32 + (lane & 15);                           // + tm*16
    const uint32_t a_off = (uint32_t)(a_row * TSTRIDE + ((lane >> 4) << 4));
    const int b_row = wn * 64 + (lane & 7) + (((lane >> 4) & 1) << 3); // + tn2*16
    const uint32_t b_off = (uint32_t)(b_row * TSTRIDE + (((lane >> 3) & 1) << 4));

    float acc[2][8][4];        // [tm][tn][q] — 64 regs
#pragma unroll
    for (int i = 0; i < 2; i++)
#pragma unroll
        for (int j = 0; j < 8; j++)
#pragma unroll
            for (int q = 0; q < 4; q++) acc[i][j][q] = 0.f;

    load_tiles(sb, 0, m0, n0, tid, 0);  CP_COMMIT();
    load_tiles(sb, 1, m0, n0, tid, BK); CP_COMMIT();

    for (int ks = 0; ks < KSTEPS; ks++) {
        CP_WAIT(1);            // stage ks resident
        __syncthreads();       // all warps finished compute(ks-1)
        if (ks + 2 < KSTEPS)
            load_tiles(sb, (ks + 2) % NSTAGES, m0, n0, tid, (ks + 2) * BK);
        CP_COMMIT();           // may be empty (keeps wait count uniform)

        const uint32_t tb = sb + (uint32_t)((ks % NSTAGES) * STAGEB);
#pragma unroll
        for (int ksub = 0; ksub < 4; ksub++) {
            const uint32_t koff = (uint32_t)(ksub * 32);  // 16 elems = 32 B
            uint32_t afrag[2][4];
#pragma unroll
            for (int tm = 0; tm < 2; tm++) {
                uint32_t addr = tb + a_off + (uint32_t)(tm * 16 * TSTRIDE) + koff;
                LDMATRIX_X4(afrag[tm], addr);
            }
            uint32_t bfrag[8][2];
#pragma unroll
            for (int tn2 = 0; tn2 < 4; tn2++) {
                uint32_t addr = tb + TILEB + b_off
                              + (uint32_t)(tn2 * 16 * TSTRIDE) + koff;
                uint32_t r[4];
                LDMATRIX_X4(r, addr);
                bfrag[2 * tn2][0] = r[0];     bfrag[2 * tn2][1] = r[1];
                bfrag[2 * tn2 + 1][0] = r[2]; bfrag[2 * tn2 + 1][1] = r[3];
            }
#pragma unroll
            for (int tm = 0; tm < 2; tm++)
#pragma unroll
                for (int tn = 0; tn < 8; tn++)
                    MMA16816(acc[tm][tn], afrag[tm], bfrag[tn]);
        }
    }

    // one-shot epilogue: per-row max/sumexp over this 128-col tile
    float rm[2][2], rs[2][2];
#pragma unroll
    for (int tm = 0; tm < 2; tm++) {
#pragma unroll
        for (int half = 0; half < 2; half++) {
            float mx = NEG_INF;
#pragma unroll
            for (int tn = 0; tn < 8; tn++)
                mx = fmaxf(mx, fmaxf(acc[tm][tn][half * 2],
                                     acc[tm][tn][half * 2 + 1]));
            mx = fmaxf(mx, __shfl_xor_sync(0xffffffffu, mx, 1));
            mx = fmaxf(mx, __shfl_xor_sync(0xffffffffu, mx, 2));
            float s = 0.f;
#pragma unroll
            for (int tn = 0; tn < 8; tn++) {
                s += __expf(acc[tm][tn][half * 2]     - mx);
                s += __expf(acc[tm][tn][half * 2 + 1] - mx);
            }
            s += __shfl_xor_sync(0xffffffffu, s, 1);
            s += __shfl_xor_sync(0xffffffffu, s, 2);
            rm[tm][half] = mx;
            rs[tm][half] = s;
        }
    }

    // merge the two N-warps (wn=0/1) per row and store tile partials
    float* s_m = (float*)smem;            // [2][128] (reuse tile smem)
    float* s_s = s_m + 256;
    __syncthreads();
    if ((lane & 3) == 0) {
#pragma unroll
        for (int tm = 0; tm < 2; tm++)
#pragma unroll
            for (int half = 0; half < 2; half++) {
                int row = wm * 32 + tm * 16 + half * 8 + (lane >> 2);
                s_m[wn * 128 + row] = rm[tm][half];
                s_s[wn * 128 + row] = rs[tm][half];
            }
    }
    __syncthreads();
    if (tid < BM) {
        float ma = s_m[tid], mb = s_m[128 + tid];
        float M = fmaxf(ma, mb);
        float S = s_s[tid] * __expf(ma - M) + s_s[128 + tid] * __expf(mb - M);
        g_pmax[(m0 + tid) * NCHUNKS + nt] = M;
        g_psum[(m0 + tid) * NCHUNKS + nt] = S;
    }
}

// ---------------- per-row finalize + last-block final reduce ----------------
__global__ void finalize_rows(const float* __restrict__ img,
                              const float* __restrict__ text,
                              const void* __restrict__ labels,
                              const float* __restrict__ scale_ptr,
                              float* __restrict__ out) {
    __shared__ int s_is64;
    __shared__ float sh[8];
    __shared__ int s_last;
    __shared__ float red[256];

    const int warp = threadIdx.x >> 5;
    const int lane = threadIdx.x & 31;
    const int row  = blockIdx.x * 8 + warp;
    const float scale = *scale_ptr;

    if (threadIdx.x < 32) {
        int is64 = detect_lab64_warp(labels, lane);
        if (lane == 0) s_is64 = is64;
    }
    __syncthreads();

    const int c = get_label(labels, row, s_is64);
    const int cnt = g_cnt[c] - 1;

    // combine 64 logsumexp partials: 2 entries per lane
    float pm0 = g_pmax[row * NCHUNKS + lane];
    float pm1 = g_pmax[row * NCHUNKS + 32 + lane];
    float M = fmaxf(pm0, pm1);
#pragma unroll
    for (int o = 16; o; o >>= 1) M = fmaxf(M, __shfl_xor_sync(0xffffffffu, M, o));
    float ps = g_psum[row * NCHUNKS + lane] * __expf(pm0 - M)
             + g_psum[row * NCHUNKS + 32 + lane] * __expf(pm1 - M);
#pragma unroll
    for (int o = 16; o; o >>= 1) ps += __shfl_xor_sync(0xffffffffu, ps, o);
    float lse = M + __logf(ps);

    // exact fp32 masked-sum dot: img_row · (S_c - text_row), float4 loads
    const float4* img4  = (const float4*)(img  + row * DDIM);
    const float4* txt4  = (const float4*)(text + row * DDIM);
    const float4* Sc4   = (const float4*)(g_S + c * DDIM);
    float d = 0.f;
#pragma unroll
    for (int g = 0; g < DDIM / 128; g++) {
        int k = g * 32 + lane;
        float4 a = img4[k], b = txt4[k], s4 = Sc4[k];
        d += a.x * (s4.x - b.x) + a.y * (s4.y - b.y)
           + a.z * (s4.z - b.z) + a.w * (s4.w - b.w);
    }
#pragma unroll
    for (int o = 16; o; o >>= 1) d += __shfl_xor_sync(0xffffffffu, d, o);

    if (lane == 0)
        sh[warp] = (cnt > 0) ? (scale * d - (float)cnt * lse) / (float)cnt : 0.f;
    __syncthreads();
    if (threadIdx.x == 0) {
        float a = 0.f;
#pragma unroll
        for (int w = 0; w < 8; w++) a += sh[w];
        g_ploss[blockIdx.x] = a;
        __threadfence();
        int old = atomicAdd(&g_done, 1);
        s_last = (old == 1023);
    }
    __syncthreads();

    // last block: deterministic final reduction of the 1024 partials
    if (s_last) {
        __threadfence();
        float a = 0.f;
        for (int i = threadIdx.x; i < 1024; i += 256) a += g_ploss[i];
        red[threadIdx.x] = a;
        __syncthreads();
        for (int s = 128; s; s >>= 1) {
            if (threadIdx.x < s) red[threadIdx.x] += red[threadIdx.x + s];
            __syncthreads();
        }
        if (threadIdx.x == 0) {
            out[0] = -red[0] / (float)NROWS;
            g_done = 0;                    // reset for next graph replay
        }
    }
}

// ---------------- launch ----------------------------------------------------
extern "C" void kernel_launch(void* const* d_in, const int* in_sizes, int n_in,
                              void* d_out, int out_size) {
    // Identify inputs by element count (robust to metadata ordering).
    const float* img   = nullptr;
    const float* text  = nullptr;
    const float* scale = nullptr;
    const void*  labels = nullptr;
    for (int i = 0; i < n_in; i++) {
        int s = in_sizes[i];
        if (s == NROWS * DDIM) {
            if (!img) img = (const float*)d_in[i];
            else      text = (const float*)d_in[i];
        } else if (s == 1) {
            scale = (const float*)d_in[i];
        } else if (s == NROWS) {
            labels = d_in[i];
        }
    }
    float* out = (float*)d_out;

    cudaFuncSetAttribute(gemm_lse_kernel,
                         cudaFuncAttributeMaxDynamicSharedMemorySize, SM_MAIN_BYTES);

    // 3 launches.
    prologue_kernel<<<SRC_BLKS + IMG_BLOCKS, 512>>>(img, text, labels, scale);
    gemm_lse_kernel<<<4096, MAIN_THREADS, SM_MAIN_BYTES>>>();
    finalize_rows<<<1024, 256>>>(img, text, labels, scale, out);
}

// round 17
// speedup vs baseline: 1.0795x; 1.0296x over previous
#include <cuda_runtime.h>
#include <cuda_bf16.h>
#include <cstdint>

// ============================================================================
// SourceAwareContrastiveLoss, GB300 — base sm_103 ISA.
// R17: prologue vectorization — text convert+srcsum role now float4-loads
// with 4 rows in flight (8 iterations, was 64 scalar ones) across 256 blocks;
// 4 rquad groups merged in smem so partial count stays 256. Img role
// unchanged. GEMM (absorbed reduceS, 256 partials, unroll 16) and finalize
// unchanged. 3 launches.
//
// loss = -(1/N) sum_i (scale*img_i·(S_{c(i)} - text_i) - cnt_i*lse_i)/cnt_i
// lse_i = logsumexp_j scale*(img_i·text_j)
// ============================================================================

#define NROWS 8192
#define DDIM  512
#define NSRC  8
#define BM    128
#define BN    128
#define BK    64
#define KSTEPS (DDIM / BK)     // 8 K-steps per tile
#define NCHUNKS 64             // one partial per 128-column tile
#define MAIN_THREADS 256
#define NSTAGES 3

#define TSTRIDE 144                    // 128 B data + 16 B pad (conflict-free ldmatrix)
#define TILEB   (128 * TSTRIDE)        // 18432 B per operand tile
#define STAGEB  (2 * TILEB)            // A + B
#define SM_MAIN_BYTES (NSTAGES * STAGEB)   // 110592 B  (x2 CTAs = 221184 <= 228KB)

#define SRC_BLKS 256                   // srcsum partial blocks (32 rows each)
#define IMG_BLOCKS 256                 // img-convert blocks in the fused prologue

// ---------------- device scratch (static: no runtime allocation) -----------
__device__ __nv_bfloat16 g_img_bf [NROWS * DDIM];   // scale * img, bf16
__device__ __nv_bfloat16 g_text_bf[NROWS * DDIM];
__device__ float g_Spart[SRC_BLKS * NSRC * DDIM];   // 4 MB
__device__ float g_S[NSRC * DDIM];
__device__ int   g_cntPart[SRC_BLKS * NSRC];
__device__ int   g_cnt[NSRC];
__device__ float g_pmax[NROWS * NCHUNKS];
__device__ float g_psum[NROWS * NCHUNKS];
__device__ float g_ploss[1024];
__device__ int   g_done;               // static-init 0; reset by last block

// ---------------- label handling --------------------------------------------
// Warp-collective dtype detect: int64 labels in [0,8) have all odd 32-bit
// words zero; 32 random int32 labels all-zero has prob 8^-32. Deterministic.
__device__ __forceinline__ int detect_lab64_warp(const void* labels, int lane) {
    int w = ((const int*)labels)[2 * lane + 1];
    unsigned nb = __ballot_sync(0xffffffffu, w != 0);
    return nb == 0u;
}

__device__ __forceinline__ int get_label(const void* p, int i, int lab64) {
    int v = lab64 ? (int)((const long long*)p)[i] : ((const int*)p)[i];
    return (v < 0) ? 0 : (v >= NSRC ? NSRC - 1 : v);
}

// ---------------- PTX helpers ----------------------------------------------
__device__ __forceinline__ uint32_t smem_to_u32(const void* p) {
    uint32_t a;
    asm("{ .reg .u64 t; cvta.to.shared.u64 t, %1; cvt.u32.u64 %0, t; }"
        : "=r"(a) : "l"(p));
    return a;
}

#define CP_ASYNC16(saddr, gptr) \
    asm volatile("cp.async.cg.shared.global [%0], [%1], 16;" \
        :: "r"(saddr), "l"(gptr))
#define CP_COMMIT() asm volatile("cp.async.commit_group;")
#define CP_WAIT(n)  asm volatile("cp.async.wait_group %0;" :: "n"(n))

#define LDMATRIX_X4(r, addr) \
    asm volatile("ldmatrix.sync.aligned.m8n8.x4.shared.b16 {%0,%1,%2,%3}, [%4];" \
        : "=r"((r)[0]), "=r"((r)[1]), "=r"((r)[2]), "=r"((r)[3]) : "r"(addr))

#define MMA16816(d, a, b) \
    asm volatile("mma.sync.aligned.m16n8k16.row.col.f32.bf16.bf16.f32 " \
        "{%0,%1,%2,%3}, {%4,%5,%6,%7}, {%8,%9}, {%0,%1,%2,%3};" \
        : "+f"((d)[0]), "+f"((d)[1]), "+f"((d)[2]), "+f"((d)[3]) \
        : "r"((a)[0]), "r"((a)[1]), "r"((a)[2]), "r"((a)[3]), \
          "r"((b)[0]), "r"((b)[1]))

// ---------------- fused prologue --------------------------------------------
// blocks [0, SRC_BLKS): text convert + class partial sums (32 rows/block,
//   float4 loads, 4 rows in flight, 8 iterations)
// blocks [SRC_BLKS, SRC_BLKS+IMG_BLOCKS): img convert (scaled), grid-stride
__global__ void prologue_kernel(const float* __restrict__ img,
                                const float* __restrict__ text,
                                const void* __restrict__ labels,
                                const float* __restrict__ scale_ptr) {
    if (blockIdx.x < SRC_BLKS) {
        // ---- text convert + srcsum ----
        __shared__ int slab[32];
        __shared__ int s_is64;
        __shared__ float4 Sv[NSRC][128];     // 16 KB class accumulators
        const int t    = threadIdx.x;        // 0..511
        const int col4 = t & 127;            // owns columns 4*col4 .. +3
        const int rq   = t >> 7;             // 0..3 row-quad group
        const int r0   = blockIdx.x * 32;

        if (t < 32) {
            int is64 = detect_lab64_warp(labels, t);
            if (t == 0) s_is64 = is64;
        }
        __syncthreads();
        if (t < 32) slab[t] = get_label(labels, r0 + t, s_is64);
        // zero Sv: 1024 float4 entries, 2 per thread
        float4 z = make_float4(0.f, 0.f, 0.f, 0.f);
        ((float4*)Sv)[t] = z;
        ((float4*)Sv)[t + 512] = z;
        __syncthreads();

        float4 s4[NSRC];
#pragma unroll
        for (int c = 0; c < NSRC; c++) s4[c] = z;

        const float4* txt4 = (const float4*)text + (size_t)r0 * 128;
        uint2* dst = (uint2*)g_text_bf + (size_t)r0 * 128;
#pragma unroll
        for (int it = 0; it < 8; it++) {
            int r = rq + it * 4;                 // 0..31
            float4 v = txt4[r * 128 + col4];
            __nv_bfloat162 lo = __floats2bfloat162_rn(v.x, v.y);
            __nv_bfloat162 hi = __floats2bfloat162_rn(v.z, v.w);
            dst[r * 128 + col4] = make_uint2(*(uint32_t*)&lo, *(uint32_t*)&hi);
            int lab = slab[r];
#pragma unroll
            for (int c = 0; c < NSRC; c++) {
                s4[c].x += (lab == c) ? v.x : 0.f;
                s4[c].y += (lab == c) ? v.y : 0.f;
                s4[c].z += (lab == c) ? v.z : 0.f;
                s4[c].w += (lab == c) ? v.w : 0.f;
            }
        }
        // merge the 4 rquad groups (serialized, conflict-free float4 adds)
#pragma unroll
        for (int g = 0; g < 4; g++) {
            if (rq == g) {
#pragma unroll
                for (int c = 0; c < NSRC; c++) {
                    float4 cur = Sv[c][col4];
                    cur.x += s4[c].x; cur.y += s4[c].y;
                    cur.z += s4[c].z; cur.w += s4[c].w;
                    Sv[c][col4] = cur;
                }
            }
            __syncthreads();
        }
        // write partials: class c row of 512 floats, coalesced
#pragma unroll
        for (int c = 0; c < NSRC; c++)
            g_Spart[(blockIdx.x * NSRC + c) * DDIM + t] = ((const float*)&Sv[c][0])[t];
        if (t < NSRC) {
            int cnt = 0;
#pragma unroll
            for (int r = 0; r < 32; r++) cnt += (slab[r] == t);
            g_cntPart[blockIdx.x * NSRC + t] = cnt;
        }
    } else {
        // ---- img convert (scaled), float4 grid-stride ----
        const int total4 = NROWS * DDIM / 4;
        const int stride = IMG_BLOCKS * 512;
        const float sc = *scale_ptr;
        for (int i = (blockIdx.x - SRC_BLKS) * 512 + threadIdx.x;
             i < total4; i += stride) {
            float4 v = ((const float4*)img)[i];
            __nv_bfloat162 lo = __floats2bfloat162_rn(sc * v.x, sc * v.y);
            __nv_bfloat162 hi = __floats2bfloat162_rn(sc * v.z, sc * v.w);
            ((uint2*)g_img_bf)[i] = make_uint2(*(uint32_t*)&lo, *(uint32_t*)&hi);
        }
    }
}

// ---------------- main fused GEMM + online logsumexp ------------------------

// issue cp.async for one BK=64 k-slice (A + B tiles) into `stage`
__device__ __forceinline__ void load_tiles(uint32_t sb, int stage,
                                           int m0, int n0, int tid, int k0) {
#pragma unroll
    for (int i = 0; i < 8; i++) {
        int idx    = i * MAIN_THREADS + tid;  // 0..2047
        int tile   = idx >> 10;               // 0=A, 1=B
        int within = idx & 1023;
        int row    = within >> 3;             // 0..127
        int c8     = within & 7;              // 16B chunks
        const __nv_bfloat16* base = tile ? g_text_bf : g_img_bf;
        int grow = (tile ? n0 : m0) + row;
        const __nv_bfloat16* g = base + grow * DDIM + k0 + c8 * 8;
        uint32_t s = sb + stage * STAGEB + tile * TILEB + row * TSTRIDE + c8 * 16;
        CP_ASYNC16(s, g);
    }
}

// grid = 4096 CTAs: (mt 0..63) x (nt 0..63); each CTA: ONE 128x128 tile.
// 8 warps: wm 0..3 (32-row strip), wn 0..1 (64-col strip)
// CTAs 0..15 additionally perform the coalesced reduceS before their tile.
__global__ void __launch_bounds__(MAIN_THREADS, 2)
gemm_lse_kernel() {
    extern __shared__ char smem[];
    uint32_t sb = smem_to_u32(smem);
    const int tid  = threadIdx.x;
    const int warp = tid >> 5;
    const int lane = tid & 31;
    const int wm = warp >> 1;           // 0..3  (M subtile)
    const int wn = warp & 1;            // 0..1  (N subtile)
    const int mt = blockIdx.x & 63;
    const int nt = blockIdx.x >> 6;     // 0..63
    const int m0 = mt * BM;
    const int n0 = nt * BN;
    const float NEG_INF = __int_as_float(0xff800000);

    // absorbed reduceS: 16 CTAs x 256 threads = 4096 outputs, coalesced
    if (blockIdx.x < 16) {
        int out = blockIdx.x * 256 + tid;
        float a = 0.f;
#pragma unroll 16
        for (int p = 0; p < SRC_BLKS; p++)
            a += g_Spart[p * (NSRC * DDIM) + out];
        g_S[out] = a;
        if (blockIdx.x == 0 && tid < NSRC) {
            int c = 0;
#pragma unroll 16
            for (int p = 0; p < SRC_BLKS; p++)
                c += g_cntPart[p * NSRC + tid];
            g_cnt[tid] = c;
        }
    }

    // ldmatrix per-lane address offsets (within an operand tile)
    const int a_row = wm * 32 + (lane & 15);                           // + tm*16
    const uint32_t a_off = (uint32_t)(a_row * TSTRIDE + ((lane >> 4) << 4));
    const int b_row = wn * 64 + (lane & 7) + (((lane >> 4) & 1) << 3); // + tn2*16
    const uint32_t b_off = (uint32_t)(b_row * TSTRIDE + (((lane >> 3) & 1) << 4));

    float acc[2][8][4];        // [tm][tn][q] — 64 regs
#pragma unroll
    for (int i = 0; i < 2; i++)
#pragma unroll
        for (int j = 0; j < 8; j++)
#pragma unroll
            for (int q = 0; q < 4; q++) acc[i][j][q] = 0.f;

    load_tiles(sb, 0, m0, n0, tid, 0);  CP_COMMIT();
    load_tiles(sb, 1, m0, n0, tid, BK); CP_COMMIT();

    for (int ks = 0; ks < KSTEPS; ks++) {
        CP_WAIT(1);            // stage ks resident
        __syncthreads();       // all warps finished compute(ks-1)
        if (ks + 2 < KSTEPS)
            load_tiles(sb, (ks + 2) % NSTAGES, m0, n0, tid, (ks + 2) * BK);
        CP_COMMIT();           // may be empty (keeps wait count uniform)

        const uint32_t tb = sb + (uint32_t)((ks % NSTAGES) * STAGEB);
#pragma unroll
        for (int ksub = 0; ksub < 4; ksub++) {
            const uint32_t koff = (uint32_t)(ksub * 32);  // 16 elems = 32 B
            uint32_t afrag[2][4];
#pragma unroll
            for (int tm = 0; tm < 2; tm++) {
                uint32_t addr = tb + a_off + (uint32_t)(tm * 16 * TSTRIDE) + koff;
                LDMATRIX_X4(afrag[tm], addr);
            }
            uint32_t bfrag[8][2];
#pragma unroll
            for (int tn2 = 0; tn2 < 4; tn2++) {
                uint32_t addr = tb + TILEB + b_off
                              + (uint32_t)(tn2 * 16 * TSTRIDE) + koff;
                uint32_t r[4];
                LDMATRIX_X4(r, addr);
                bfrag[2 * tn2][0] = r[0];     bfrag[2 * tn2][1] = r[1];
                bfrag[2 * tn2 + 1][0] = r[2]; bfrag[2 * tn2 + 1][1] = r[3];
            }
#pragma unroll
            for (int tm = 0; tm < 2; tm++)
#pragma unroll
                for (int tn = 0; tn < 8; tn++)
                    MMA16816(acc[tm][tn], afrag[tm], bfrag[tn]);
        }
    }

    // one-shot epilogue: per-row max/sumexp over this 128-col tile
    float rm[2][2], rs[2][2];
#pragma unroll
    for (int tm = 0; tm < 2; tm++) {
#pragma unroll
        for (int half = 0; half < 2; half++) {
            float mx = NEG_INF;
#pragma unroll
            for (int tn = 0; tn < 8; tn++)
                mx = fmaxf(mx, fmaxf(acc[tm][tn][half * 2],
                                     acc[tm][tn][half * 2 + 1]));
            mx = fmaxf(mx, __shfl_xor_sync(0xffffffffu, mx, 1));
            mx = fmaxf(mx, __shfl_xor_sync(0xffffffffu, mx, 2));
            float s = 0.f;
#pragma unroll
            for (int tn = 0; tn < 8; tn++) {
                s += __expf(acc[tm][tn][half * 2]     - mx);
                s += __expf(acc[tm][tn][half * 2 + 1] - mx);
            }
            s += __shfl_xor_sync(0xffffffffu, s, 1);
            s += __shfl_xor_sync(0xffffffffu, s, 2);
            rm[tm][half] = mx;
            rs[tm][half] = s;
        }
    }

    // merge the two N-warps (wn=0/1) per row and store tile partials
    float* s_m = (float*)smem;            // [2][128] (reuse tile smem)
    float* s_s = s_m + 256;
    __syncthreads();
    if ((lane & 3) == 0) {
#pragma unroll
        for (int tm = 0; tm < 2; tm++)
#pragma unroll
            for (int half = 0; half < 2; half++) {
                int row = wm * 32 + tm * 16 + half * 8 + (lane >> 2);
                s_m[wn * 128 + row] = rm[tm][half];
                s_s[wn * 128 + row] = rs[tm][half];
            }
    }
    __syncthreads();
    if (tid < BM) {
        float ma = s_m[tid], mb = s_m[128 + tid];
        float M = fmaxf(ma, mb);
        float S = s_s[tid] * __expf(ma - M) + s_s[128 + tid] * __expf(mb - M);
        g_pmax[(m0 + tid) * NCHUNKS + nt] = M;
        g_psum[(m0 + tid) * NCHUNKS + nt] = S;
    }
}

// ---------------- per-row finalize + last-block final reduce ----------------
__global__ void finalize_rows(const float* __restrict__ img,
                              const float* __restrict__ text,
                              const void* __restrict__ labels,
                              const float* __restrict__ scale_ptr,
                              float* __restrict__ out) {
    __shared__ int s_is64;
    __shared__ float sh[8];
    __shared__ int s_last;
    __shared__ float red[256];

    const int warp = threadIdx.x >> 5;
    const int lane = threadIdx.x & 31;
    const int row  = blockIdx.x * 8 + warp;
    const float scale = *scale_ptr;

    if (threadIdx.x < 32) {
        int is64 = detect_lab64_warp(labels, lane);
        if (lane == 0) s_is64 = is64;
    }
    __syncthreads();

    const int c = get_label(labels, row, s_is64);
    const int cnt = g_cnt[c] - 1;

    // combine 64 logsumexp partials: 2 entries per lane
    float pm0 = g_pmax[row * NCHUNKS + lane];
    float pm1 = g_pmax[row * NCHUNKS + 32 + lane];
    float M = fmaxf(pm0, pm1);
#pragma unroll
    for (int o = 16; o; o >>= 1) M = fmaxf(M, __shfl_xor_sync(0xffffffffu, M, o));
    float ps = g_psum[row * NCHUNKS + lane] * __expf(pm0 - M)
             + g_psum[row * NCHUNKS + 32 + lane] * __expf(pm1 - M);
#pragma unroll
    for (int o = 16; o; o >>= 1) ps += __shfl_xor_sync(0xffffffffu, ps, o);
    float lse = M + __logf(ps);

    // exact fp32 masked-sum dot: img_row · (S_c - text_row), float4 loads
    const float4* img4  = (const float4*)(img  + row * DDIM);
    const float4* txt4  = (const float4*)(text + row * DDIM);
    const float4* Sc4   = (const float4*)(g_S + c * DDIM);
    float d = 0.f;
#pragma unroll
    for (int g = 0; g < DDIM / 128; g++) {
        int k = g * 32 + lane;
        float4 a = img4[k], b = txt4[k], s4 = Sc4[k];
        d += a.x * (s4.x - b.x) + a.y * (s4.y - b.y)
           + a.z * (s4.z - b.z) + a.w * (s4.w - b.w);
    }
#pragma unroll
    for (int o = 16; o; o >>= 1) d += __shfl_xor_sync(0xffffffffu, d, o);

    if (lane == 0)
        sh[warp] = (cnt > 0) ? (scale * d - (float)cnt * lse) / (float)cnt : 0.f;
    __syncthreads();
    if (threadIdx.x == 0) {
        float a = 0.f;
#pragma unroll
        for (int w = 0; w < 8; w++) a += sh[w];
        g_ploss[blockIdx.x] = a;
        __threadfence();
        int old = atomicAdd(&g_done, 1);
        s_last = (old == 1023);
    }
    __syncthreads();

    // last block: deterministic final reduction of the 1024 partials
    if (s_last) {
        __threadfence();
        float a = 0.f;
        for (int i = threadIdx.x; i < 1024; i += 256) a += g_ploss[i];
        red[threadIdx.x] = a;
        __syncthreads();
        for (int s = 128; s; s >>= 1) {
            if (threadIdx.x < s) red[threadIdx.x] += red[threadIdx.x + s];
            __syncthreads();
        }
        if (threadIdx.x == 0) {
            out[0] = -red[0] / (float)NROWS;
            g_done = 0;                    // reset for next graph replay
        }
    }
}

// ---------------- launch ----------------------------------------------------
extern "C" void kernel_launch(void* const* d_in, const int* in_sizes, int n_in,
                              void* d_out, int out_size) {
    // Identify inputs by element count (robust to metadata ordering).
    const float* img   = nullptr;
    const float* text  = nullptr;
    const float* scale = nullptr;
    const void*  labels = nullptr;
    for (int i = 0; i < n_in; i++) {
        int s = in_sizes[i];
        if (s == NROWS * DDIM) {
            if (!img) img = (const float*)d_in[i];
            else      text = (const float*)d_in[i];
        } else if (s == 1) {
            scale = (const float*)d_in[i];
        } else if (s == NROWS) {
            labels = d_in[i];
        }
    }
    float* out = (float*)d_out;

    cudaFuncSetAttribute(gemm_lse_kernel,
                         cudaFuncAttributeMaxDynamicSharedMemorySize, SM_MAIN_BYTES);

    // 3 launches.
    prologue_kernel<<<SRC_BLKS + IMG_BLOCKS, 512>>>(img, text, labels, scale);
    gemm_lse_kernel<<<4096, MAIN_THREADS, SM_MAIN_BYTES>>>();
    finalize_rows<<<1024, 256>>>(img, text, labels, scale, out);
}